// round 2
// baseline (speedup 1.0000x reference)
#include <cuda_runtime.h>

// ---------------- scratch (static device globals; no allocation) ----------------
__device__ float d_h1[8 * 256 * 1024];      // after dup conv  (8MB)
__device__ float d_h2[8 * 64 * 2048];       // after c1 conv   (4MB)
__device__ float d_xx[8 * 2048];            // per-point squared norms
__device__ float d_g1[8 * 64];              // global max feature
__device__ float d_g2[8 * 128];             // after g-path MLP
__device__ int   d_idx[8 * 2048 * 4];       // top-4 neighbor indices
__device__ float d_feat[8 * 128 * 8192];    // edge features     (32MB)
__device__ float d_fa[8 * 64 * 8192];       // ping              (16MB)
__device__ float d_fb[8 * 64 * 8192];       // pong              (16MB)
__device__ float d_local[8 * 64 * 2048];    // max over k        (4MB)
__device__ float d_final[8 * 192 * 2048];   // concat            (12MB)
__device__ float d_h4[8 * 256 * 2048];      // head hidden       (16MB)

// ---------------- packed f32x2 helpers ----------------
typedef unsigned long long u64;

__device__ __forceinline__ u64 pack2(float x, float y) {
    u64 r;
    asm("mov.b64 %0, {%1, %2};" : "=l"(r) : "f"(x), "f"(y));
    return r;
}
__device__ __forceinline__ void unpack2(u64 v, float& x, float& y) {
    asm("mov.b64 {%0, %1}, %2;" : "=f"(x), "=f"(y) : "l"(v));
}
__device__ __forceinline__ u64 fma2(u64 a, u64 b, u64 c) {
    u64 d;
    asm("fma.rn.f32x2 %0, %1, %2, %3;" : "=l"(d) : "l"(a), "l"(b), "l"(c));
    return d;
}

// ---------------- generic tiled GEMM, f32x2 microkernel ----------------
// C[o,n] = relu((sum_c A[o,c]*B[c,n])*s[o]+bias[o]); tile 64x64, Kt 16, 256 thr, 4x4 micro.
// kmax: instead of writing 64x64 tile, write max over groups of 4 cols (k-dim) to C
// laid out [o, 2048] (fused local_max for the edge convs).
__global__ void __launch_bounds__(256) gemm_sbr(
    const float* __restrict__ A, const float* __restrict__ B, float* __restrict__ C,
    const float* __restrict__ scale, const float* __restrict__ bias,
    int K, int N, long sB, long sC, int kmax)
{
    __shared__ float2 As[16][64];   // duplicated (v,v) along o
    __shared__ float  Bs[16][64];
    const int bz = blockIdx.z;
    const float* Bp = B + (long)bz * sB;
    float* Cp = C + (long)bz * sC;
    const int o0 = blockIdx.y * 64;
    const int n0 = blockIdx.x * 64;
    const int tid = threadIdx.x;
    const int tx = tid & 15, ty = tid >> 4;

    const int ar = tid >> 2;                // 0..63 (A row within tile)
    const int aq = (tid & 3) * 4;           // 0..12 (A k offset)
    const int bk = tid >> 4;                // 0..15 (B k row)
    const int bn = (tid & 15) * 4;          // 0..60 (B n offset)

    u64 acc[4][2];
#pragma unroll
    for (int i = 0; i < 4; ++i) { acc[i][0] = 0ULL; acc[i][1] = 0ULL; }

    for (int k0 = 0; k0 < K; k0 += 16) {
        float4 av = *(const float4*)&A[(long)(o0 + ar) * K + k0 + aq];
        As[aq + 0][ar] = make_float2(av.x, av.x);
        As[aq + 1][ar] = make_float2(av.y, av.y);
        As[aq + 2][ar] = make_float2(av.z, av.z);
        As[aq + 3][ar] = make_float2(av.w, av.w);
        *(float4*)&Bs[bk][bn] = *(const float4*)&Bp[(long)(k0 + bk) * N + n0 + bn];
        __syncthreads();
#pragma unroll
        for (int k = 0; k < 16; ++k) {
            ulonglong2 a01 = *(const ulonglong2*)&As[k][ty * 4];      // dup(a0),dup(a1)
            ulonglong2 a23 = *(const ulonglong2*)&As[k][ty * 4 + 2];  // dup(a2),dup(a3)
            ulonglong2 b   = *(const ulonglong2*)&Bs[k][tx * 4];      // (b0,b1),(b2,b3)
            acc[0][0] = fma2(a01.x, b.x, acc[0][0]);
            acc[0][1] = fma2(a01.x, b.y, acc[0][1]);
            acc[1][0] = fma2(a01.y, b.x, acc[1][0]);
            acc[1][1] = fma2(a01.y, b.y, acc[1][1]);
            acc[2][0] = fma2(a23.x, b.x, acc[2][0]);
            acc[2][1] = fma2(a23.x, b.y, acc[2][1]);
            acc[3][0] = fma2(a23.y, b.x, acc[3][0]);
            acc[3][1] = fma2(a23.y, b.y, acc[3][1]);
        }
        __syncthreads();
    }

#pragma unroll
    for (int i = 0; i < 4; ++i) {
        int o = o0 + ty * 4 + i;
        float sv = scale ? scale[o] : 1.0f;
        float bv = bias[o];
        float4 r;
        unpack2(acc[i][0], r.x, r.y);
        unpack2(acc[i][1], r.z, r.w);
        r.x = fmaxf(fmaf(r.x, sv, bv), 0.f);
        r.y = fmaxf(fmaf(r.y, sv, bv), 0.f);
        r.z = fmaxf(fmaf(r.z, sv, bv), 0.f);
        r.w = fmaxf(fmaf(r.w, sv, bv), 0.f);
        if (kmax) {
            // cols n0+tx*4 .. +3 are one point's 4 neighbors: point = n0/4 + tx
            float m = fmaxf(fmaxf(r.x, r.y), fmaxf(r.z, r.w));
            Cp[(long)o * 2048 + (n0 >> 2) + tx] = m;
        } else {
            *(float4*)&Cp[(long)o * N + n0 + tx * 4] = r;
        }
    }
}

// ---------------- xx[b,n] = sum_c h2^2 (same FMA chain order as the dot in topk) --------
__global__ void xx_kernel()
{
    int t = blockIdx.x * blockDim.x + threadIdx.x;   // 8*2048
    int b = t >> 11, n = t & 2047;
    const float* h = d_h2 + (long)b * 64 * 2048;
    float acc = 0.f;
#pragma unroll
    for (int c = 0; c < 64; ++c) {
        float v = h[c * 2048 + n];
        acc = fmaf(v, v, acc);
    }
    d_xx[t] = acc;
}

// ---------------- g1[b,c] = max_n h2[b,c,n] ----------------
__global__ void gmax_kernel()
{
    int bc = blockIdx.x;          // 0..511
    int tid = threadIdx.x;        // 128 threads
    const float4* p = (const float4*)(d_h2 + (long)bc * 2048);
    float m = -1e30f;
    for (int i = tid; i < 512; i += 128) {
        float4 v = p[i];
        m = fmaxf(m, fmaxf(fmaxf(v.x, v.y), fmaxf(v.z, v.w)));
    }
    __shared__ float sm[128];
    sm[tid] = m;
    __syncthreads();
    for (int s = 64; s > 0; s >>= 1) {
        if (tid < s) sm[tid] = fmaxf(sm[tid], sm[tid + s]);
        __syncthreads();
    }
    if (tid == 0) d_g1[bc] = sm[0];
}

// ---------------- pairwise distances + stable top-4, f32x2, split-m ----------------
// grid (16, 8), block 256. Threads 0..127 own points n (m in [0,1024)),
// threads 128..255 own the same points (m in [1024,2048)). smem merge at end.
__device__ __forceinline__ void topk_insert(float pd, int m,
    float& v0, float& v1, float& v2, float& v3,
    int& i0, int& i1, int& i2, int& i3)
{
    if (pd > v3) {                       // strict > keeps earliest index on ties
        if (pd > v1) {
            if (pd > v0) {
                v3 = v2; i3 = i2; v2 = v1; i2 = i1; v1 = v0; i1 = i0;
                v0 = pd; i0 = m;
            } else {
                v3 = v2; i3 = i2; v2 = v1; i2 = i1;
                v1 = pd; i1 = m;
            }
        } else {
            if (pd > v2) { v3 = v2; i3 = i2; v2 = pd; i2 = m; }
            else         { v3 = pd; i3 = m; }
        }
    }
}

__global__ void __launch_bounds__(256) pairwise_topk()
{
    __shared__ float sm[64][128];    // cols 0-63: half-A tile, 64-127: half-B tile
    __shared__ float sxx[128];
    __shared__ float mv[128][4];
    __shared__ int   mi[128][4];

    const int b = blockIdx.y;
    const int tid = threadIdx.x;
    const int lane = tid & 127;                  // point slot
    const int half = tid >> 7;                   // 0: m in [0,1024), 1: [1024,2048)
    const int n = blockIdx.x * 128 + lane;
    const float* h = d_h2 + (long)b * 64 * 2048;

    float hn[64];
#pragma unroll
    for (int c = 0; c < 64; ++c) hn[c] = h[c * 2048 + n];
    const float xn = d_xx[b * 2048 + n];

    float v0 = -1e30f, v1 = -1e30f, v2 = -1e30f, v3 = -1e30f;
    int i0 = 0, i1 = 0, i2 = 0, i3 = 0;

    const int mybase = half * 64;                // my smem column base

    for (int it = 0; it < 16; ++it) {
        __syncthreads();
        {
            // fill: columns 0-63 <- m = it*64 + col; columns 64-127 <- 1024 + it*64 + col-64
            for (int idx = tid; idx < 64 * 128; idx += 256) {
                int c = idx >> 7, col = idx & 127;
                int m = (col < 64) ? (it * 64 + col) : (1024 + it * 64 + (col - 64));
                sm[c][col] = h[c * 2048 + m];
            }
            if (tid < 128) {
                int m = (tid < 64) ? (it * 64 + tid) : (1024 + it * 64 + (tid - 64));
                sxx[tid] = d_xx[b * 2048 + m];
            }
        }
        __syncthreads();

        const int m0 = half * 1024 + it * 64;
        for (int mm = 0; mm < 64; mm += 8) {
            u64 dA = 0ULL, dB = 0ULL, dC = 0ULL, dD = 0ULL;
#pragma unroll 8
            for (int c = 0; c < 64; ++c) {
                ulonglong2 s01 = *(const ulonglong2*)&sm[c][mybase + mm];
                ulonglong2 s23 = *(const ulonglong2*)&sm[c][mybase + mm + 4];
                u64 hd = pack2(hn[c], hn[c]);
                dA = fma2(hd, s01.x, dA);
                dB = fma2(hd, s01.y, dB);
                dC = fma2(hd, s23.x, dC);
                dD = fma2(hd, s23.y, dD);
            }
            float dot[8];
            unpack2(dA, dot[0], dot[1]);
            unpack2(dB, dot[2], dot[3]);
            unpack2(dC, dot[4], dot[5]);
            unpack2(dD, dot[6], dot[7]);
#pragma unroll
            for (int j = 0; j < 8; ++j) {
                float pd = fmaf(2.0f, dot[j], -xn) - sxx[mybase + mm + j];
                topk_insert(pd, m0 + mm + j, v0, v1, v2, v3, i0, i1, i2, i3);
            }
        }
    }

    // merge: half B writes its top-4 to smem, half A inserts them (B's m are all larger)
    __syncthreads();
    if (half == 1) {
        mv[lane][0] = v0; mv[lane][1] = v1; mv[lane][2] = v2; mv[lane][3] = v3;
        mi[lane][0] = i0; mi[lane][1] = i1; mi[lane][2] = i2; mi[lane][3] = i3;
    }
    __syncthreads();
    if (half == 0) {
#pragma unroll
        for (int j = 0; j < 4; ++j)
            topk_insert(mv[lane][j], mi[lane][j], v0, v1, v2, v3, i0, i1, i2, i3);
        int base = (b * 2048 + n) * 4;
        d_idx[base + 0] = i0;
        d_idx[base + 1] = i1;
        d_idx[base + 2] = i2;
        d_idx[base + 3] = i3;
    }
}

// ---------------- build edge features: feat[b,c,(n,k)] ----------------
__global__ void build_feat()
{
    long t = (long)blockIdx.x * blockDim.x + threadIdx.x;   // 8*128*8192
    int k = (int)(t & 3);
    int n = (int)((t >> 2) & 2047);
    int c = (int)((t >> 13) & 127);
    int b = (int)(t >> 20);
    const float* h = d_h2 + (long)b * 64 * 2048;
    float v;
    if (c < 64) {
        int j = d_idx[((long)b * 2048 + n) * 4 + k];
        v = h[c * 2048 + j] - h[c * 2048 + n];
    } else {
        v = h[(c - 64) * 2048 + n];
    }
    d_feat[t] = v;
}

// ---------------- global-feature MLP: 64 -> 128 -> 128 ----------------
__global__ void gpath(const float* __restrict__ W3a, const float* __restrict__ s3a,
                      const float* __restrict__ b3a, const float* __restrict__ W3b,
                      const float* __restrict__ s3b, const float* __restrict__ b3b)
{
    __shared__ float gin[64];
    __shared__ float gmid[128];
    int b = blockIdx.x, tid = threadIdx.x;
    if (tid < 64) gin[tid] = d_g1[b * 64 + tid];
    __syncthreads();
    float acc = 0.f;
#pragma unroll
    for (int c = 0; c < 64; ++c) acc = fmaf(W3a[tid * 64 + c], gin[c], acc);
    gmid[tid] = fmaxf(fmaf(acc, s3a[tid], b3a[tid]), 0.f);
    __syncthreads();
    acc = 0.f;
#pragma unroll
    for (int c = 0; c < 128; ++c) acc = fmaf(W3b[tid * 128 + c], gmid[c], acc);
    d_g2[b * 128 + tid] = fmaxf(fmaf(acc, s3b[tid], b3b[tid]), 0.f);
}

// ---------------- final[b,c,n] = c<64 ? local : broadcast g2 ----------------
__global__ void concat_final()
{
    long t = (long)blockIdx.x * blockDim.x + threadIdx.x;   // 8*192*2048
    int n = (int)(t & 2047);
    int c = (int)((t >> 11) % 192);
    int b = (int)(t / (192 * 2048));
    float v = (c < 64) ? d_local[((long)b * 64 + c) * 2048 + n]
                       : d_g2[b * 128 + (c - 64)];
    d_final[t] = v;
}

// ---------------- head: out[b,o,n] = W4b[o,:] @ h4[b,:,n] + bias ----------------
__global__ void out_kernel(const float* __restrict__ W4b,
                           const float* __restrict__ bias4b,
                           float* __restrict__ out)
{
    int t = blockIdx.x * blockDim.x + threadIdx.x;  // 8*2048
    int b = t >> 11, n = t & 2047;
    const float* h = d_h4 + (long)b * 256 * 2048;
    float a0 = bias4b[0], a1 = bias4b[1], a2 = bias4b[2];
#pragma unroll 4
    for (int c = 0; c < 256; ++c) {
        float hv = h[c * 2048 + n];
        a0 = fmaf(W4b[c], hv, a0);
        a1 = fmaf(W4b[256 + c], hv, a1);
        a2 = fmaf(W4b[512 + c], hv, a2);
    }
    out[((long)b * 3 + 0) * 2048 + n] = a0;
    out[((long)b * 3 + 1) * 2048 + n] = a1;
    out[((long)b * 3 + 2) * 2048 + n] = a2;
}

// ---------------- host launcher ----------------
extern "C" void kernel_launch(void* const* d_in, const int* in_sizes, int n_in,
                              void* d_out, int out_size)
{
    const float* x      = (const float*)d_in[0];
    const float* W_dup  = (const float*)d_in[1];
    const float* s_dup  = (const float*)d_in[2];
    const float* b_dup  = (const float*)d_in[3];
    const float* W_c1   = (const float*)d_in[4];
    const float* s_c1   = (const float*)d_in[5];
    const float* b_c1   = (const float*)d_in[6];
    const float* W2a    = (const float*)d_in[7];
    const float* s2a    = (const float*)d_in[8];
    const float* b2a    = (const float*)d_in[9];
    const float* W2b    = (const float*)d_in[10];
    const float* s2b    = (const float*)d_in[11];
    const float* b2b    = (const float*)d_in[12];
    const float* W2c    = (const float*)d_in[13];
    const float* s2c    = (const float*)d_in[14];
    const float* b2c    = (const float*)d_in[15];
    const float* W3a    = (const float*)d_in[16];
    const float* s3a    = (const float*)d_in[17];
    const float* b3a    = (const float*)d_in[18];
    const float* W3b    = (const float*)d_in[19];
    const float* s3b    = (const float*)d_in[20];
    const float* b3b    = (const float*)d_in[21];
    const float* W4a    = (const float*)d_in[22];
    const float* bias4a = (const float*)d_in[23];
    const float* W4b    = (const float*)d_in[24];
    const float* bias4b = (const float*)d_in[25];

    float *p_h1, *p_h2, *p_feat, *p_fa, *p_fb, *p_local, *p_final, *p_h4;
    cudaGetSymbolAddress((void**)&p_h1, d_h1);
    cudaGetSymbolAddress((void**)&p_h2, d_h2);
    cudaGetSymbolAddress((void**)&p_feat, d_feat);
    cudaGetSymbolAddress((void**)&p_fa, d_fa);
    cudaGetSymbolAddress((void**)&p_fb, d_fb);
    cudaGetSymbolAddress((void**)&p_local, d_local);
    cudaGetSymbolAddress((void**)&p_final, d_final);
    cudaGetSymbolAddress((void**)&p_h4, d_h4);

    // L1: (256x128) @ x[b](128x1024) -> h1
    gemm_sbr<<<dim3(16, 4, 8), 256>>>(W_dup, x, p_h1, s_dup, b_dup,
                                      128, 1024, 131072L, 262144L, 0);
    // L2: (64x128) @ h1[b] reinterpreted as (128x2048) -> h2
    gemm_sbr<<<dim3(32, 1, 8), 256>>>(W_c1, p_h1, p_h2, s_c1, b_c1,
                                      128, 2048, 262144L, 131072L, 0);
    xx_kernel<<<64, 256>>>();
    gmax_kernel<<<512, 128>>>();
    pairwise_topk<<<dim3(16, 8), 256>>>();
    build_feat<<<32768, 256>>>();
    // conv2a: (64x128) @ feat[b](128x8192) -> fa
    gemm_sbr<<<dim3(128, 1, 8), 256>>>(W2a, p_feat, p_fa, s2a, b2a,
                                       128, 8192, 1048576L, 524288L, 0);
    // conv2b: (64x64) @ fa -> fb
    gemm_sbr<<<dim3(128, 1, 8), 256>>>(W2b, p_fa, p_fb, s2b, b2b,
                                       64, 8192, 524288L, 524288L, 0);
    // conv2c: (64x64) @ fb -> local (fused max over k in epilogue)
    gemm_sbr<<<dim3(128, 1, 8), 256>>>(W2c, p_fb, p_local, s2c, b2c,
                                       64, 8192, 524288L, 131072L, 1);
    gpath<<<8, 128>>>(W3a, s3a, b3a, W3b, s3b, b3b);
    concat_final<<<12288, 256>>>();
    // head hidden: (256x192) @ final[b](192x2048) -> h4 (bias+relu, no scale)
    gemm_sbr<<<dim3(32, 4, 8), 256>>>(W4a, p_final, p_h4, nullptr, bias4a,
                                      192, 2048, 393216L, 524288L, 0);
    out_kernel<<<64, 256>>>(W4b, bias4b, (float*)d_out);
}

// round 3
// speedup vs baseline: 1.6962x; 1.6962x over previous
#include <cuda_runtime.h>

// ---------------- scratch (static device globals; no allocation) ----------------
__device__ float d_h1[8 * 256 * 1024];      // after dup conv  (8MB)
__device__ float d_h2[8 * 64 * 2048];       // after c1 conv   (4MB)
__device__ float d_xx[8 * 2048];            // per-point squared norms
__device__ float d_g1[8 * 64];              // global max feature
__device__ float d_g2[8 * 128];             // after g-path MLP
__device__ int   d_idx[8 * 2048 * 4];       // top-4 neighbor indices
__device__ float d_feat[8 * 128 * 8192];    // edge features     (32MB)
__device__ float d_fa[8 * 64 * 8192];       // ping              (16MB)
__device__ float d_fb[8 * 64 * 8192];       // pong              (16MB)
__device__ float d_local[8 * 64 * 2048];    // max over k        (4MB)
__device__ float d_final[8 * 192 * 2048];   // concat            (12MB)
__device__ float d_h4[8 * 256 * 2048];      // head hidden       (16MB)

// =====================================================================
// GEMM A: 128(O) x 128(N) tile, 256 threads, 8x8 micro-tile, Ktile 16.
// C[o,n] = relu((sum_c A[o,c]*B[c,n]) * s[o] + bias[o])
// =====================================================================
__global__ void __launch_bounds__(256) gemmA(
    const float* __restrict__ A, const float* __restrict__ B, float* __restrict__ C,
    const float* __restrict__ scale, const float* __restrict__ bias,
    int K, int N, long sB, long sC)
{
    __shared__ float As[16][128];
    __shared__ float Bs[16][128];
    const float* Bp = B + (long)blockIdx.z * sB;
    float* Cp = C + (long)blockIdx.z * sC;
    const int o0 = blockIdx.y * 128;
    const int n0 = blockIdx.x * 128;
    const int tid = threadIdx.x;
    const int tx = tid & 15, ty = tid >> 4;

    const int ar = tid >> 1;             // 0..127
    const int aq = (tid & 1) * 8;        // 0 or 8
    const int bk = tid >> 4;             // 0..15
    const int bn = (tid & 15) * 8;       // 0..120

    float acc[8][8];
#pragma unroll
    for (int i = 0; i < 8; ++i)
#pragma unroll
        for (int j = 0; j < 8; ++j) acc[i][j] = 0.f;

    for (int k0 = 0; k0 < K; k0 += 16) {
        float4 a0 = *(const float4*)&A[(long)(o0 + ar) * K + k0 + aq];
        float4 a1 = *(const float4*)&A[(long)(o0 + ar) * K + k0 + aq + 4];
        As[aq + 0][ar] = a0.x; As[aq + 1][ar] = a0.y;
        As[aq + 2][ar] = a0.z; As[aq + 3][ar] = a0.w;
        As[aq + 4][ar] = a1.x; As[aq + 5][ar] = a1.y;
        As[aq + 6][ar] = a1.z; As[aq + 7][ar] = a1.w;
        *(float4*)&Bs[bk][bn]     = *(const float4*)&Bp[(long)(k0 + bk) * N + n0 + bn];
        *(float4*)&Bs[bk][bn + 4] = *(const float4*)&Bp[(long)(k0 + bk) * N + n0 + bn + 4];
        __syncthreads();
#pragma unroll 4
        for (int k = 0; k < 16; ++k) {
            float a[8], b[8];
            *(float4*)&a[0] = *(const float4*)&As[k][ty * 8];
            *(float4*)&a[4] = *(const float4*)&As[k][ty * 8 + 4];
            *(float4*)&b[0] = *(const float4*)&Bs[k][tx * 8];
            *(float4*)&b[4] = *(const float4*)&Bs[k][tx * 8 + 4];
#pragma unroll
            for (int i = 0; i < 8; ++i)
#pragma unroll
                for (int j = 0; j < 8; ++j)
                    acc[i][j] = fmaf(a[i], b[j], acc[i][j]);
        }
        __syncthreads();
    }

#pragma unroll
    for (int i = 0; i < 8; ++i) {
        int o = o0 + ty * 8 + i;
        float sv = scale ? scale[o] : 1.0f;
        float bv = bias[o];
        float r[8];
#pragma unroll
        for (int j = 0; j < 8; ++j)
            r[j] = fmaxf(fmaf(acc[i][j], sv, bv), 0.f);
        *(float4*)&Cp[(long)o * N + n0 + tx * 8]     = *(float4*)&r[0];
        *(float4*)&Cp[(long)o * N + n0 + tx * 8 + 4] = *(float4*)&r[4];
    }
}

// =====================================================================
// GEMM B: 64(O) x 256(N) tile, 256 threads, 8x8 micro-tile, Ktile 16.
// kmax=1: write max over each group of 4 n (the k-neighbor dim) to C[o,2048].
// =====================================================================
__global__ void __launch_bounds__(256) gemmB(
    const float* __restrict__ A, const float* __restrict__ B, float* __restrict__ C,
    const float* __restrict__ scale, const float* __restrict__ bias,
    int K, int N, long sB, long sC, int kmax)
{
    __shared__ float As[16][64];
    __shared__ float Bs[16][256];
    const float* Bp = B + (long)blockIdx.z * sB;
    float* Cp = C + (long)blockIdx.z * sC;
    const int n0 = blockIdx.x * 256;
    const int tid = threadIdx.x;
    const int tx = tid & 31, ty = tid >> 5;   // ty 0..7 (o), tx 0..31 (n)

    const int ar = tid >> 2;             // 0..63
    const int aq = (tid & 3) * 4;        // 0,4,8,12
    const int bk = tid >> 4;             // 0..15
    const int bn = (tid & 15) * 16;      // 0..240

    float acc[8][8];
#pragma unroll
    for (int i = 0; i < 8; ++i)
#pragma unroll
        for (int j = 0; j < 8; ++j) acc[i][j] = 0.f;

    for (int k0 = 0; k0 < K; k0 += 16) {
        float4 a0 = *(const float4*)&A[(long)ar * K + k0 + aq];
        As[aq + 0][ar] = a0.x; As[aq + 1][ar] = a0.y;
        As[aq + 2][ar] = a0.z; As[aq + 3][ar] = a0.w;
#pragma unroll
        for (int q = 0; q < 4; ++q)
            *(float4*)&Bs[bk][bn + q * 4] =
                *(const float4*)&Bp[(long)(k0 + bk) * N + n0 + bn + q * 4];
        __syncthreads();
#pragma unroll 4
        for (int k = 0; k < 16; ++k) {
            float a[8], b[8];
            *(float4*)&a[0] = *(const float4*)&As[k][ty * 8];
            *(float4*)&a[4] = *(const float4*)&As[k][ty * 8 + 4];
            *(float4*)&b[0] = *(const float4*)&Bs[k][tx * 8];
            *(float4*)&b[4] = *(const float4*)&Bs[k][tx * 8 + 4];
#pragma unroll
            for (int i = 0; i < 8; ++i)
#pragma unroll
                for (int j = 0; j < 8; ++j)
                    acc[i][j] = fmaf(a[i], b[j], acc[i][j]);
        }
        __syncthreads();
    }

#pragma unroll
    for (int i = 0; i < 8; ++i) {
        int o = ty * 8 + i;
        float sv = scale ? scale[o] : 1.0f;
        float bv = bias[o];
        float r[8];
#pragma unroll
        for (int j = 0; j < 8; ++j)
            r[j] = fmaxf(fmaf(acc[i][j], sv, bv), 0.f);
        if (kmax) {
            // cols n0+tx*8 .. +7 = points (n0>>2)+tx*2 and +1
            int p = (n0 >> 2) + tx * 2;
            Cp[(long)o * 2048 + p]     = fmaxf(fmaxf(r[0], r[1]), fmaxf(r[2], r[3]));
            Cp[(long)o * 2048 + p + 1] = fmaxf(fmaxf(r[4], r[5]), fmaxf(r[6], r[7]));
        } else {
            *(float4*)&Cp[(long)o * N + n0 + tx * 8]     = *(float4*)&r[0];
            *(float4*)&Cp[(long)o * N + n0 + tx * 8 + 4] = *(float4*)&r[4];
        }
    }
}

// ---------------- xx[b,n] = sum_c h2^2 (same FMA chain order as the dot) --------
__global__ void xx_kernel()
{
    int t = blockIdx.x * blockDim.x + threadIdx.x;   // 8*2048
    int b = t >> 11, n = t & 2047;
    const float* h = d_h2 + (long)b * 64 * 2048;
    float acc = 0.f;
#pragma unroll
    for (int c = 0; c < 64; ++c) {
        float v = h[c * 2048 + n];
        acc = fmaf(v, v, acc);
    }
    d_xx[t] = acc;
}

// ---------------- g1[b,c] = max_n h2[b,c,n] ----------------
__global__ void gmax_kernel()
{
    int bc = blockIdx.x;          // 0..511
    int tid = threadIdx.x;        // 256 threads
    const float4* p = (const float4*)(d_h2 + (long)bc * 2048);
    float4 v0 = p[tid];
    float4 v1 = p[tid + 256];
    float m = fmaxf(fmaxf(fmaxf(v0.x, v0.y), fmaxf(v0.z, v0.w)),
                    fmaxf(fmaxf(v1.x, v1.y), fmaxf(v1.z, v1.w)));
    __shared__ float sm[256];
    sm[tid] = m;
    __syncthreads();
    for (int s = 128; s > 0; s >>= 1) {
        if (tid < s) sm[tid] = fmaxf(sm[tid], sm[tid + s]);
        __syncthreads();
    }
    if (tid == 0) d_g1[bc] = sm[0];
}

// ---------------- stable top-4 insert (strict > keeps earliest index on ties) ----
__device__ __forceinline__ void topk_insert(float pd, int m,
    float& v0, float& v1, float& v2, float& v3,
    int& i0, int& i1, int& i2, int& i3)
{
    if (pd > v3) {
        if (pd > v1) {
            if (pd > v0) {
                v3 = v2; i3 = i2; v2 = v1; i2 = i1; v1 = v0; i1 = i0;
                v0 = pd; i0 = m;
            } else {
                v3 = v2; i3 = i2; v2 = v1; i2 = i1;
                v1 = pd; i1 = m;
            }
        } else {
            if (pd > v2) { v3 = v2; i3 = i2; v2 = pd; i2 = m; }
            else         { v3 = pd; i3 = m; }
        }
    }
}

// ---------------- pairwise distances + top-4, 4-way m-split ----------------
// grid (16, 8), block 512. lane = point slot (128 pts/block); quarter = m range.
__global__ void __launch_bounds__(512) pairwise_topk()
{
    __shared__ float sm[64][256];    // col = quarter*64 + j
    __shared__ float sxx[256];
    __shared__ float mv[3][128][4];
    __shared__ int   mi[3][128][4];

    const int b = blockIdx.y;
    const int tid = threadIdx.x;
    const int lane = tid & 127;
    const int quarter = tid >> 7;     // 0..3
    const int n = blockIdx.x * 128 + lane;
    const float* h = d_h2 + (long)b * 64 * 2048;

    float hn[64];
#pragma unroll
    for (int c = 0; c < 64; ++c) hn[c] = h[c * 2048 + n];
    const float xn = d_xx[b * 2048 + n];

    float v0 = -1e30f, v1 = -1e30f, v2 = -1e30f, v3 = -1e30f;
    int i0 = 0, i1 = 0, i2 = 0, i3 = 0;

    const int base = quarter * 64;

    for (int it = 0; it < 8; ++it) {
        __syncthreads();
        for (int idx = tid; idx < 64 * 256; idx += 512) {
            int c = idx >> 8, col = idx & 255;
            int m = (col >> 6) * 512 + it * 64 + (col & 63);
            sm[c][col] = h[c * 2048 + m];
        }
        if (tid < 256) {
            int m = (tid >> 6) * 512 + it * 64 + (tid & 63);
            sxx[tid] = d_xx[b * 2048 + m];
        }
        __syncthreads();

        const int m0 = quarter * 512 + it * 64;
#pragma unroll 1
        for (int mm = 0; mm < 64; mm += 8) {
            float dot[8];
#pragma unroll
            for (int j = 0; j < 8; ++j) dot[j] = 0.f;
#pragma unroll
            for (int c = 0; c < 64; ++c) {
                float4 s0 = *(const float4*)&sm[c][base + mm];      // broadcast
                float4 s1 = *(const float4*)&sm[c][base + mm + 4];  // broadcast
                float hv = hn[c];
                dot[0] = fmaf(hv, s0.x, dot[0]);
                dot[1] = fmaf(hv, s0.y, dot[1]);
                dot[2] = fmaf(hv, s0.z, dot[2]);
                dot[3] = fmaf(hv, s0.w, dot[3]);
                dot[4] = fmaf(hv, s1.x, dot[4]);
                dot[5] = fmaf(hv, s1.y, dot[5]);
                dot[6] = fmaf(hv, s1.z, dot[6]);
                dot[7] = fmaf(hv, s1.w, dot[7]);
            }
#pragma unroll
            for (int j = 0; j < 8; ++j) {
                float pd = fmaf(2.0f, dot[j], -xn) - sxx[base + mm + j];
                topk_insert(pd, m0 + mm + j, v0, v1, v2, v3, i0, i1, i2, i3);
            }
        }
    }

    // merge: quarters 1..3 publish; quarter 0 merges in ascending-m order.
    __syncthreads();
    if (quarter > 0) {
        mv[quarter - 1][lane][0] = v0; mv[quarter - 1][lane][1] = v1;
        mv[quarter - 1][lane][2] = v2; mv[quarter - 1][lane][3] = v3;
        mi[quarter - 1][lane][0] = i0; mi[quarter - 1][lane][1] = i1;
        mi[quarter - 1][lane][2] = i2; mi[quarter - 1][lane][3] = i3;
    }
    __syncthreads();
    if (quarter == 0) {
#pragma unroll
        for (int q = 0; q < 3; ++q)
#pragma unroll
            for (int j = 0; j < 4; ++j)
                topk_insert(mv[q][lane][j], mi[q][lane][j],
                            v0, v1, v2, v3, i0, i1, i2, i3);
        int baseo = (b * 2048 + n) * 4;
        d_idx[baseo + 0] = i0;
        d_idx[baseo + 1] = i1;
        d_idx[baseo + 2] = i2;
        d_idx[baseo + 3] = i3;
    }
}

// ---------------- build edge features: feat[b,c,(n,k)] ----------------
__global__ void build_feat()
{
    long t = (long)blockIdx.x * blockDim.x + threadIdx.x;   // 8*128*8192
    int k = (int)(t & 3);
    int n = (int)((t >> 2) & 2047);
    int c = (int)((t >> 13) & 127);
    int b = (int)(t >> 20);
    const float* h = d_h2 + (long)b * 64 * 2048;
    float v;
    if (c < 64) {
        int j = d_idx[((long)b * 2048 + n) * 4 + k];
        v = h[c * 2048 + j] - h[c * 2048 + n];
    } else {
        v = h[(c - 64) * 2048 + n];
    }
    d_feat[t] = v;
}

// ---------------- global-feature MLP: 64 -> 128 -> 128 ----------------
__global__ void gpath(const float* __restrict__ W3a, const float* __restrict__ s3a,
                      const float* __restrict__ b3a, const float* __restrict__ W3b,
                      const float* __restrict__ s3b, const float* __restrict__ b3b)
{
    __shared__ float gin[64];
    __shared__ float gmid[128];
    int b = blockIdx.x, tid = threadIdx.x;
    if (tid < 64) gin[tid] = d_g1[b * 64 + tid];
    __syncthreads();
    float acc = 0.f;
#pragma unroll
    for (int c = 0; c < 64; ++c) acc = fmaf(W3a[tid * 64 + c], gin[c], acc);
    gmid[tid] = fmaxf(fmaf(acc, s3a[tid], b3a[tid]), 0.f);
    __syncthreads();
    acc = 0.f;
#pragma unroll
    for (int c = 0; c < 128; ++c) acc = fmaf(W3b[tid * 128 + c], gmid[c], acc);
    d_g2[b * 128 + tid] = fmaxf(fmaf(acc, s3b[tid], b3b[tid]), 0.f);
}

// ---------------- final[b,c,n] = c<64 ? local : broadcast g2 ----------------
__global__ void concat_final()
{
    long t = (long)blockIdx.x * blockDim.x + threadIdx.x;   // 8*192*2048
    int n = (int)(t & 2047);
    int c = (int)((t >> 11) % 192);
    int b = (int)(t / (192 * 2048));
    float v = (c < 64) ? d_local[((long)b * 64 + c) * 2048 + n]
                       : d_g2[b * 128 + (c - 64)];
    d_final[t] = v;
}

// ---------------- head: out[b,o,n] = W4b[o,:] @ h4[b,:,n] + bias ----------------
__global__ void out_kernel(const float* __restrict__ W4b,
                           const float* __restrict__ bias4b,
                           float* __restrict__ out)
{
    int t = blockIdx.x * blockDim.x + threadIdx.x;  // 8*2048
    int b = t >> 11, n = t & 2047;
    const float* h = d_h4 + (long)b * 256 * 2048;
    float a0 = bias4b[0], a1 = bias4b[1], a2 = bias4b[2];
#pragma unroll 4
    for (int c = 0; c < 256; ++c) {
        float hv = h[c * 2048 + n];
        a0 = fmaf(W4b[c], hv, a0);
        a1 = fmaf(W4b[256 + c], hv, a1);
        a2 = fmaf(W4b[512 + c], hv, a2);
    }
    out[((long)b * 3 + 0) * 2048 + n] = a0;
    out[((long)b * 3 + 1) * 2048 + n] = a1;
    out[((long)b * 3 + 2) * 2048 + n] = a2;
}

// ---------------- host launcher ----------------
extern "C" void kernel_launch(void* const* d_in, const int* in_sizes, int n_in,
                              void* d_out, int out_size)
{
    const float* x      = (const float*)d_in[0];
    const float* W_dup  = (const float*)d_in[1];
    const float* s_dup  = (const float*)d_in[2];
    const float* b_dup  = (const float*)d_in[3];
    const float* W_c1   = (const float*)d_in[4];
    const float* s_c1   = (const float*)d_in[5];
    const float* b_c1   = (const float*)d_in[6];
    const float* W2a    = (const float*)d_in[7];
    const float* s2a    = (const float*)d_in[8];
    const float* b2a    = (const float*)d_in[9];
    const float* W2b    = (const float*)d_in[10];
    const float* s2b    = (const float*)d_in[11];
    const float* b2b    = (const float*)d_in[12];
    const float* W2c    = (const float*)d_in[13];
    const float* s2c    = (const float*)d_in[14];
    const float* b2c    = (const float*)d_in[15];
    const float* W3a    = (const float*)d_in[16];
    const float* s3a    = (const float*)d_in[17];
    const float* b3a    = (const float*)d_in[18];
    const float* W3b    = (const float*)d_in[19];
    const float* s3b    = (const float*)d_in[20];
    const float* b3b    = (const float*)d_in[21];
    const float* W4a    = (const float*)d_in[22];
    const float* bias4a = (const float*)d_in[23];
    const float* W4b    = (const float*)d_in[24];
    const float* bias4b = (const float*)d_in[25];

    float *p_h1, *p_h2, *p_feat, *p_fa, *p_fb, *p_local, *p_final, *p_h4;
    cudaGetSymbolAddress((void**)&p_h1, d_h1);
    cudaGetSymbolAddress((void**)&p_h2, d_h2);
    cudaGetSymbolAddress((void**)&p_feat, d_feat);
    cudaGetSymbolAddress((void**)&p_fa, d_fa);
    cudaGetSymbolAddress((void**)&p_fb, d_fb);
    cudaGetSymbolAddress((void**)&p_local, d_local);
    cudaGetSymbolAddress((void**)&p_final, d_final);
    cudaGetSymbolAddress((void**)&p_h4, d_h4);

    // L1: (256x128) @ x[b](128x1024) -> h1
    gemmA<<<dim3(8, 2, 8), 256>>>(W_dup, x, p_h1, s_dup, b_dup,
                                  128, 1024, 131072L, 262144L);
    // L2: (64x128) @ h1[b] reinterpreted as (128x2048) -> h2
    gemmB<<<dim3(8, 1, 8), 256>>>(W_c1, p_h1, p_h2, s_c1, b_c1,
                                  128, 2048, 262144L, 131072L, 0);
    xx_kernel<<<64, 256>>>();
    gmax_kernel<<<512, 256>>>();
    pairwise_topk<<<dim3(16, 8), 512>>>();
    build_feat<<<32768, 256>>>();
    // conv2a: (64x128) @ feat[b](128x8192) -> fa
    gemmB<<<dim3(32, 1, 8), 256>>>(W2a, p_feat, p_fa, s2a, b2a,
                                   128, 8192, 1048576L, 524288L, 0);
    // conv2b: (64x64) @ fa -> fb
    gemmB<<<dim3(32, 1, 8), 256>>>(W2b, p_fa, p_fb, s2b, b2b,
                                   64, 8192, 524288L, 524288L, 0);
    // conv2c: (64x64) @ fb -> local (fused max over k in epilogue)
    gemmB<<<dim3(32, 1, 8), 256>>>(W2c, p_fb, p_local, s2c, b2c,
                                   64, 8192, 524288L, 131072L, 1);
    gpath<<<8, 128>>>(W3a, s3a, b3a, W3b, s3b, b3b);
    concat_final<<<12288, 256>>>();
    // head hidden: (256x192) @ final[b](192x2048) -> h4 (bias+relu, no scale)
    gemmA<<<dim3(16, 2, 8), 256>>>(W4a, p_final, p_h4, nullptr, bias4a,
                                   192, 2048, 393216L, 524288L);
    out_kernel<<<64, 256>>>(W4b, bias4b, (float*)d_out);
}

// round 4
// speedup vs baseline: 1.7036x; 1.0044x over previous
#include <cuda_runtime.h>

// ---------------- scratch (static device globals; no allocation) ----------------
__device__ float d_h1[8 * 256 * 1024];      // after dup conv  (8MB)
__device__ float d_h2[8 * 64 * 2048];       // after c1 conv   (4MB)
__device__ float d_xx[8 * 2048];            // per-point squared norms
__device__ float d_g1[8 * 64];              // global max feature
__device__ float d_g2[8 * 128];             // after g-path MLP
__device__ int   d_idx[8 * 2048 * 4];       // top-4 neighbor indices
__device__ float d_feat[8 * 128 * 8192];    // edge features     (32MB)
__device__ float d_fa[8 * 64 * 8192];       // ping              (16MB)
__device__ float d_fb[8 * 64 * 8192];       // pong              (16MB)
__device__ float d_local[8 * 64 * 2048];    // max over k        (4MB)
__device__ float d_final[8 * 192 * 2048];   // concat            (12MB)
__device__ float d_h4[8 * 256 * 2048];      // head hidden       (16MB)

// =====================================================================
// GEMM A: 128(O) x 128(N) tile, 256 threads, 8x8 micro-tile, Ktile 16.
// C[o,n] = relu((sum_c A[o,c]*B[c,n]) * s[o] + bias[o])
// =====================================================================
__global__ void __launch_bounds__(256) gemmA(
    const float* __restrict__ A, const float* __restrict__ B, float* __restrict__ C,
    const float* __restrict__ scale, const float* __restrict__ bias,
    int K, int N, long sB, long sC)
{
    __shared__ float As[16][128];
    __shared__ float Bs[16][128];
    const float* Bp = B + (long)blockIdx.z * sB;
    float* Cp = C + (long)blockIdx.z * sC;
    const int o0 = blockIdx.y * 128;
    const int n0 = blockIdx.x * 128;
    const int tid = threadIdx.x;
    const int tx = tid & 15, ty = tid >> 4;

    const int ar = tid >> 1;             // 0..127
    const int aq = (tid & 1) * 8;        // 0 or 8
    const int bk = tid >> 4;             // 0..15
    const int bn = (tid & 15) * 8;       // 0..120

    float acc[8][8];
#pragma unroll
    for (int i = 0; i < 8; ++i)
#pragma unroll
        for (int j = 0; j < 8; ++j) acc[i][j] = 0.f;

    for (int k0 = 0; k0 < K; k0 += 16) {
        float4 a0 = *(const float4*)&A[(long)(o0 + ar) * K + k0 + aq];
        float4 a1 = *(const float4*)&A[(long)(o0 + ar) * K + k0 + aq + 4];
        As[aq + 0][ar] = a0.x; As[aq + 1][ar] = a0.y;
        As[aq + 2][ar] = a0.z; As[aq + 3][ar] = a0.w;
        As[aq + 4][ar] = a1.x; As[aq + 5][ar] = a1.y;
        As[aq + 6][ar] = a1.z; As[aq + 7][ar] = a1.w;
        *(float4*)&Bs[bk][bn]     = *(const float4*)&Bp[(long)(k0 + bk) * N + n0 + bn];
        *(float4*)&Bs[bk][bn + 4] = *(const float4*)&Bp[(long)(k0 + bk) * N + n0 + bn + 4];
        __syncthreads();
#pragma unroll 4
        for (int k = 0; k < 16; ++k) {
            float a[8], b[8];
            *(float4*)&a[0] = *(const float4*)&As[k][ty * 8];
            *(float4*)&a[4] = *(const float4*)&As[k][ty * 8 + 4];
            *(float4*)&b[0] = *(const float4*)&Bs[k][tx * 8];
            *(float4*)&b[4] = *(const float4*)&Bs[k][tx * 8 + 4];
#pragma unroll
            for (int i = 0; i < 8; ++i)
#pragma unroll
                for (int j = 0; j < 8; ++j)
                    acc[i][j] = fmaf(a[i], b[j], acc[i][j]);
        }
        __syncthreads();
    }

#pragma unroll
    for (int i = 0; i < 8; ++i) {
        int o = o0 + ty * 8 + i;
        float sv = scale ? scale[o] : 1.0f;
        float bv = bias[o];
        float r[8];
#pragma unroll
        for (int j = 0; j < 8; ++j)
            r[j] = fmaxf(fmaf(acc[i][j], sv, bv), 0.f);
        *(float4*)&Cp[(long)o * N + n0 + tx * 8]     = *(float4*)&r[0];
        *(float4*)&Cp[(long)o * N + n0 + tx * 8 + 4] = *(float4*)&r[4];
    }
}

// =====================================================================
// GEMM B: 64(O) x 256(N) tile, 256 threads, 8x8 micro-tile, Ktile 16.
// kmax=1: write max over each group of 4 n (the k-neighbor dim) to C[o,2048].
// =====================================================================
__global__ void __launch_bounds__(256) gemmB(
    const float* __restrict__ A, const float* __restrict__ B, float* __restrict__ C,
    const float* __restrict__ scale, const float* __restrict__ bias,
    int K, int N, long sB, long sC, int kmax)
{
    __shared__ float As[16][64];
    __shared__ float Bs[16][256];
    const float* Bp = B + (long)blockIdx.z * sB;
    float* Cp = C + (long)blockIdx.z * sC;
    const int n0 = blockIdx.x * 256;
    const int tid = threadIdx.x;
    const int tx = tid & 31, ty = tid >> 5;   // ty 0..7 (o), tx 0..31 (n)

    const int ar = tid >> 2;             // 0..63
    const int aq = (tid & 3) * 4;        // 0,4,8,12
    const int bk = tid >> 4;             // 0..15
    const int bn = (tid & 15) * 16;      // 0..240

    float acc[8][8];
#pragma unroll
    for (int i = 0; i < 8; ++i)
#pragma unroll
        for (int j = 0; j < 8; ++j) acc[i][j] = 0.f;

    for (int k0 = 0; k0 < K; k0 += 16) {
        float4 a0 = *(const float4*)&A[(long)ar * K + k0 + aq];
        As[aq + 0][ar] = a0.x; As[aq + 1][ar] = a0.y;
        As[aq + 2][ar] = a0.z; As[aq + 3][ar] = a0.w;
#pragma unroll
        for (int q = 0; q < 4; ++q)
            *(float4*)&Bs[bk][bn + q * 4] =
                *(const float4*)&Bp[(long)(k0 + bk) * N + n0 + bn + q * 4];
        __syncthreads();
#pragma unroll 4
        for (int k = 0; k < 16; ++k) {
            float a[8], b[8];
            *(float4*)&a[0] = *(const float4*)&As[k][ty * 8];
            *(float4*)&a[4] = *(const float4*)&As[k][ty * 8 + 4];
            *(float4*)&b[0] = *(const float4*)&Bs[k][tx * 8];
            *(float4*)&b[4] = *(const float4*)&Bs[k][tx * 8 + 4];
#pragma unroll
            for (int i = 0; i < 8; ++i)
#pragma unroll
                for (int j = 0; j < 8; ++j)
                    acc[i][j] = fmaf(a[i], b[j], acc[i][j]);
        }
        __syncthreads();
    }

#pragma unroll
    for (int i = 0; i < 8; ++i) {
        int o = ty * 8 + i;
        float sv = scale ? scale[o] : 1.0f;
        float bv = bias[o];
        float r[8];
#pragma unroll
        for (int j = 0; j < 8; ++j)
            r[j] = fmaxf(fmaf(acc[i][j], sv, bv), 0.f);
        if (kmax) {
            // cols n0+tx*8 .. +7 = points (n0>>2)+tx*2 and +1
            int p = (n0 >> 2) + tx * 2;
            Cp[(long)o * 2048 + p]     = fmaxf(fmaxf(r[0], r[1]), fmaxf(r[2], r[3]));
            Cp[(long)o * 2048 + p + 1] = fmaxf(fmaxf(r[4], r[5]), fmaxf(r[6], r[7]));
        } else {
            *(float4*)&Cp[(long)o * N + n0 + tx * 8]     = *(float4*)&r[0];
            *(float4*)&Cp[(long)o * N + n0 + tx * 8 + 4] = *(float4*)&r[4];
        }
    }
}

// ---------------- xx[b,n] = sum_c h2^2 (same FMA chain order as the dot) --------
__global__ void xx_kernel()
{
    int t = blockIdx.x * blockDim.x + threadIdx.x;   // 8*2048
    int b = t >> 11, n = t & 2047;
    const float* h = d_h2 + (long)b * 64 * 2048;
    float acc = 0.f;
#pragma unroll
    for (int c = 0; c < 64; ++c) {
        float v = h[c * 2048 + n];
        acc = fmaf(v, v, acc);
    }
    d_xx[t] = acc;
}

// ---------------- g1[b,c] = max_n h2[b,c,n] ----------------
__global__ void gmax_kernel()
{
    int bc = blockIdx.x;          // 0..511
    int tid = threadIdx.x;        // 256 threads
    const float4* p = (const float4*)(d_h2 + (long)bc * 2048);
    float4 v0 = p[tid];
    float4 v1 = p[tid + 256];
    float m = fmaxf(fmaxf(fmaxf(v0.x, v0.y), fmaxf(v0.z, v0.w)),
                    fmaxf(fmaxf(v1.x, v1.y), fmaxf(v1.z, v1.w)));
    __shared__ float sm[256];
    sm[tid] = m;
    __syncthreads();
    for (int s = 128; s > 0; s >>= 1) {
        if (tid < s) sm[tid] = fmaxf(sm[tid], sm[tid + s]);
        __syncthreads();
    }
    if (tid == 0) d_g1[bc] = sm[0];
}

// ---------------- stable top-4 insert (strict > keeps earliest index on ties) ----
__device__ __forceinline__ void topk_insert(float pd, int m,
    float& v0, float& v1, float& v2, float& v3,
    int& i0, int& i1, int& i2, int& i3)
{
    if (pd > v3) {
        if (pd > v1) {
            if (pd > v0) {
                v3 = v2; i3 = i2; v2 = v1; i2 = i1; v1 = v0; i1 = i0;
                v0 = pd; i0 = m;
            } else {
                v3 = v2; i3 = i2; v2 = v1; i2 = i1;
                v1 = pd; i1 = m;
            }
        } else {
            if (pd > v2) { v3 = v2; i3 = i2; v2 = pd; i2 = m; }
            else         { v3 = pd; i3 = m; }
        }
    }
}

// ---------------- pairwise distances + top-4, 4-way m-split ----------------
// grid (16, 8), block 512. lane = point slot (128 pts/block); quarter = m range.
__global__ void __launch_bounds__(512) pairwise_topk()
{
    __shared__ float sm[64][256];    // col = quarter*64 + j
    __shared__ float sxx[256];
    __shared__ float mv[3][128][4];
    __shared__ int   mi[3][128][4];

    const int b = blockIdx.y;
    const int tid = threadIdx.x;
    const int lane = tid & 127;
    const int quarter = tid >> 7;     // 0..3
    const int n = blockIdx.x * 128 + lane;
    const float* h = d_h2 + (long)b * 64 * 2048;

    float hn[64];
#pragma unroll
    for (int c = 0; c < 64; ++c) hn[c] = h[c * 2048 + n];
    const float xn = d_xx[b * 2048 + n];

    float v0 = -1e30f, v1 = -1e30f, v2 = -1e30f, v3 = -1e30f;
    int i0 = 0, i1 = 0, i2 = 0, i3 = 0;

    const int base = quarter * 64;

    for (int it = 0; it < 8; ++it) {
        __syncthreads();
        for (int idx = tid; idx < 64 * 256; idx += 512) {
            int c = idx >> 8, col = idx & 255;
            int m = (col >> 6) * 512 + it * 64 + (col & 63);
            sm[c][col] = h[c * 2048 + m];
        }
        if (tid < 256) {
            int m = (tid >> 6) * 512 + it * 64 + (tid & 63);
            sxx[tid] = d_xx[b * 2048 + m];
        }
        __syncthreads();

        const int m0 = quarter * 512 + it * 64;
#pragma unroll 1
        for (int mm = 0; mm < 64; mm += 8) {
            float dot[8];
#pragma unroll
            for (int j = 0; j < 8; ++j) dot[j] = 0.f;
#pragma unroll
            for (int c = 0; c < 64; ++c) {
                float4 s0 = *(const float4*)&sm[c][base + mm];      // broadcast
                float4 s1 = *(const float4*)&sm[c][base + mm + 4];  // broadcast
                float hv = hn[c];
                dot[0] = fmaf(hv, s0.x, dot[0]);
                dot[1] = fmaf(hv, s0.y, dot[1]);
                dot[2] = fmaf(hv, s0.z, dot[2]);
                dot[3] = fmaf(hv, s0.w, dot[3]);
                dot[4] = fmaf(hv, s1.x, dot[4]);
                dot[5] = fmaf(hv, s1.y, dot[5]);
                dot[6] = fmaf(hv, s1.z, dot[6]);
                dot[7] = fmaf(hv, s1.w, dot[7]);
            }
#pragma unroll
            for (int j = 0; j < 8; ++j) {
                float pd = fmaf(2.0f, dot[j], -xn) - sxx[base + mm + j];
                topk_insert(pd, m0 + mm + j, v0, v1, v2, v3, i0, i1, i2, i3);
            }
        }
    }

    // merge: quarters 1..3 publish; quarter 0 merges in ascending-m order.
    __syncthreads();
    if (quarter > 0) {
        mv[quarter - 1][lane][0] = v0; mv[quarter - 1][lane][1] = v1;
        mv[quarter - 1][lane][2] = v2; mv[quarter - 1][lane][3] = v3;
        mi[quarter - 1][lane][0] = i0; mi[quarter - 1][lane][1] = i1;
        mi[quarter - 1][lane][2] = i2; mi[quarter - 1][lane][3] = i3;
    }
    __syncthreads();
    if (quarter == 0) {
#pragma unroll
        for (int q = 0; q < 3; ++q)
#pragma unroll
            for (int j = 0; j < 4; ++j)
                topk_insert(mv[q][lane][j], mi[q][lane][j],
                            v0, v1, v2, v3, i0, i1, i2, i3);
        int baseo = (b * 2048 + n) * 4;
        d_idx[baseo + 0] = i0;
        d_idx[baseo + 1] = i1;
        d_idx[baseo + 2] = i2;
        d_idx[baseo + 3] = i3;
    }
}

// ---------------- build edge features: feat[b,c,(n,k)] ----------------
__global__ void build_feat()
{
    long t = (long)blockIdx.x * blockDim.x + threadIdx.x;   // 8*128*8192
    int k = (int)(t & 3);
    int n = (int)((t >> 2) & 2047);
    int c = (int)((t >> 13) & 127);
    int b = (int)(t >> 20);
    const float* h = d_h2 + (long)b * 64 * 2048;
    float v;
    if (c < 64) {
        int j = d_idx[((long)b * 2048 + n) * 4 + k];
        v = h[c * 2048 + j] - h[c * 2048 + n];
    } else {
        v = h[(c - 64) * 2048 + n];
    }
    d_feat[t] = v;
}

// ---------------- global-feature MLP: 64 -> 128 -> 128 ----------------
__global__ void gpath(const float* __restrict__ W3a, const float* __restrict__ s3a,
                      const float* __restrict__ b3a, const float* __restrict__ W3b,
                      const float* __restrict__ s3b, const float* __restrict__ b3b)
{
    __shared__ float gin[64];
    __shared__ float gmid[128];
    int b = blockIdx.x, tid = threadIdx.x;
    if (tid < 64) gin[tid] = d_g1[b * 64 + tid];
    __syncthreads();
    float acc = 0.f;
#pragma unroll
    for (int c = 0; c < 64; ++c) acc = fmaf(W3a[tid * 64 + c], gin[c], acc);
    gmid[tid] = fmaxf(fmaf(acc, s3a[tid], b3a[tid]), 0.f);
    __syncthreads();
    acc = 0.f;
#pragma unroll
    for (int c = 0; c < 128; ++c) acc = fmaf(W3b[tid * 128 + c], gmid[c], acc);
    d_g2[b * 128 + tid] = fmaxf(fmaf(acc, s3b[tid], b3b[tid]), 0.f);
}

// ---------------- final[b,c,n] = c<64 ? local : broadcast g2 ----------------
__global__ void concat_final()
{
    long t = (long)blockIdx.x * blockDim.x + threadIdx.x;   // 8*192*2048
    int n = (int)(t & 2047);
    int c = (int)((t >> 11) % 192);
    int b = (int)(t / (192 * 2048));
    float v = (c < 64) ? d_local[((long)b * 64 + c) * 2048 + n]
                       : d_g2[b * 128 + (c - 64)];
    d_final[t] = v;
}

// ---------------- head: out[b,o,n] = W4b[o,:] @ h4[b,:,n] + bias ----------------
__global__ void out_kernel(const float* __restrict__ W4b,
                           const float* __restrict__ bias4b,
                           float* __restrict__ out)
{
    int t = blockIdx.x * blockDim.x + threadIdx.x;  // 8*2048
    int b = t >> 11, n = t & 2047;
    const float* h = d_h4 + (long)b * 256 * 2048;
    float a0 = bias4b[0], a1 = bias4b[1], a2 = bias4b[2];
#pragma unroll 4
    for (int c = 0; c < 256; ++c) {
        float hv = h[c * 2048 + n];
        a0 = fmaf(W4b[c], hv, a0);
        a1 = fmaf(W4b[256 + c], hv, a1);
        a2 = fmaf(W4b[512 + c], hv, a2);
    }
    out[((long)b * 3 + 0) * 2048 + n] = a0;
    out[((long)b * 3 + 1) * 2048 + n] = a1;
    out[((long)b * 3 + 2) * 2048 + n] = a2;
}

// ---------------- host launcher ----------------
extern "C" void kernel_launch(void* const* d_in, const int* in_sizes, int n_in,
                              void* d_out, int out_size)
{
    const float* x      = (const float*)d_in[0];
    const float* W_dup  = (const float*)d_in[1];
    const float* s_dup  = (const float*)d_in[2];
    const float* b_dup  = (const float*)d_in[3];
    const float* W_c1   = (const float*)d_in[4];
    const float* s_c1   = (const float*)d_in[5];
    const float* b_c1   = (const float*)d_in[6];
    const float* W2a    = (const float*)d_in[7];
    const float* s2a    = (const float*)d_in[8];
    const float* b2a    = (const float*)d_in[9];
    const float* W2b    = (const float*)d_in[10];
    const float* s2b    = (const float*)d_in[11];
    const float* b2b    = (const float*)d_in[12];
    const float* W2c    = (const float*)d_in[13];
    const float* s2c    = (const float*)d_in[14];
    const float* b2c    = (const float*)d_in[15];
    const float* W3a    = (const float*)d_in[16];
    const float* s3a    = (const float*)d_in[17];
    const float* b3a    = (const float*)d_in[18];
    const float* W3b    = (const float*)d_in[19];
    const float* s3b    = (const float*)d_in[20];
    const float* b3b    = (const float*)d_in[21];
    const float* W4a    = (const float*)d_in[22];
    const float* bias4a = (const float*)d_in[23];
    const float* W4b    = (const float*)d_in[24];
    const float* bias4b = (const float*)d_in[25];

    float *p_h1, *p_h2, *p_feat, *p_fa, *p_fb, *p_local, *p_final, *p_h4;
    cudaGetSymbolAddress((void**)&p_h1, d_h1);
    cudaGetSymbolAddress((void**)&p_h2, d_h2);
    cudaGetSymbolAddress((void**)&p_feat, d_feat);
    cudaGetSymbolAddress((void**)&p_fa, d_fa);
    cudaGetSymbolAddress((void**)&p_fb, d_fb);
    cudaGetSymbolAddress((void**)&p_local, d_local);
    cudaGetSymbolAddress((void**)&p_final, d_final);
    cudaGetSymbolAddress((void**)&p_h4, d_h4);

    // L1: (256x128) @ x[b](128x1024) -> h1
    gemmA<<<dim3(8, 2, 8), 256>>>(W_dup, x, p_h1, s_dup, b_dup,
                                  128, 1024, 131072L, 262144L);
    // L2: (64x128) @ h1[b] reinterpreted as (128x2048) -> h2
    gemmB<<<dim3(8, 1, 8), 256>>>(W_c1, p_h1, p_h2, s_c1, b_c1,
                                  128, 2048, 262144L, 131072L, 0);
    xx_kernel<<<64, 256>>>();
    gmax_kernel<<<512, 256>>>();
    pairwise_topk<<<dim3(16, 8), 512>>>();
    build_feat<<<32768, 256>>>();
    // conv2a: (64x128) @ feat[b](128x8192) -> fa
    gemmB<<<dim3(32, 1, 8), 256>>>(W2a, p_feat, p_fa, s2a, b2a,
                                   128, 8192, 1048576L, 524288L, 0);
    // conv2b: (64x64) @ fa -> fb
    gemmB<<<dim3(32, 1, 8), 256>>>(W2b, p_fa, p_fb, s2b, b2b,
                                   64, 8192, 524288L, 524288L, 0);
    // conv2c: (64x64) @ fb -> local (fused max over k in epilogue)
    gemmB<<<dim3(32, 1, 8), 256>>>(W2c, p_fb, p_local, s2c, b2c,
                                   64, 8192, 524288L, 131072L, 1);
    gpath<<<8, 128>>>(W3a, s3a, b3a, W3b, s3b, b3b);
    concat_final<<<12288, 256>>>();
    // head hidden: (256x192) @ final[b](192x2048) -> h4 (bias+relu, no scale)
    gemmA<<<dim3(16, 2, 8), 256>>>(W4a, p_final, p_h4, nullptr, bias4a,
                                   192, 2048, 393216L, 524288L);
    out_kernel<<<64, 256>>>(W4b, bias4b, (float*)d_out);
}

// round 5
// speedup vs baseline: 1.8655x; 1.0950x over previous
#include <cuda_runtime.h>

// ---------------- scratch (static device globals; no allocation) ----------------
__device__ float d_h1[8 * 256 * 1024];      // after dup conv  (8MB)
__device__ float d_h2[8 * 64 * 2048];       // after c1 conv   (4MB)
__device__ float d_xx[8 * 2048];            // per-point squared norms
__device__ float d_g1[8 * 64];              // global max feature
__device__ float d_g2[8 * 128];             // after g-path MLP
__device__ int   d_idx[8 * 2048 * 4];       // top-4 neighbor indices
__device__ float d_feat[8 * 64 * 8192];     // gathered nb features (16MB)
__device__ float d_fa[8 * 64 * 8192];       // ping              (16MB)
__device__ float d_fb[8 * 64 * 8192];       // pong              (16MB)
__device__ float d_local[8 * 64 * 2048];    // max over k        (4MB)
__device__ float d_h4[8 * 256 * 2048];      // head hidden       (16MB)
__device__ float d_T[8 * 64 * 2048];        // ctr-term for conv2a (4MB)
__device__ float d_gb[8 * 256];             // per-(b,o) folded head bias
__device__ float d_W4a_c[256 * 64];         // W4a[:,0:64] compact
__device__ float d_W2a_nb[64 * 64];         // W2a[:,0:64] compact
__device__ float d_W2a_diff[64 * 64];       // W2a[:,64:128]-W2a[:,0:64]

// ---------------- weight repack ----------------
__global__ void prep_weights(const float* __restrict__ W4a,
                             const float* __restrict__ W2a)
{
    int t = blockIdx.x * blockDim.x + threadIdx.x;
    if (t < 16384) {
        int o = t >> 6, c = t & 63;
        d_W4a_c[t] = W4a[o * 192 + c];
    } else if (t < 16384 + 4096) {
        int i = t - 16384;
        int o = i >> 6, c = i & 63;
        d_W2a_nb[i]   = W2a[o * 128 + c];
        d_W2a_diff[i] = W2a[o * 128 + 64 + c] - W2a[o * 128 + c];
    }
}

// =====================================================================
// GEMM A: 128(O) x 128(N) tile, 256 threads, 8x8 micro-tile, Ktile 16.
// C = relu((A@B)*s + bias[z*sBias + o]); scale may be nullptr (=>1).
// =====================================================================
__global__ void __launch_bounds__(256) gemmA(
    const float* __restrict__ A, const float* __restrict__ B, float* __restrict__ C,
    const float* __restrict__ scale, const float* __restrict__ bias,
    int K, int N, long sB, long sC, long sBias)
{
    __shared__ float As[16][128];
    __shared__ float Bs[16][128];
    const float* Bp = B + (long)blockIdx.z * sB;
    float* Cp = C + (long)blockIdx.z * sC;
    const float* biasp = bias + (long)blockIdx.z * sBias;
    const int o0 = blockIdx.y * 128;
    const int n0 = blockIdx.x * 128;
    const int tid = threadIdx.x;
    const int tx = tid & 15, ty = tid >> 4;

    const int ar = tid >> 1;             // 0..127
    const int aq = (tid & 1) * 8;        // 0 or 8
    const int bk = tid >> 4;             // 0..15
    const int bn = (tid & 15) * 8;       // 0..120

    float acc[8][8];
#pragma unroll
    for (int i = 0; i < 8; ++i)
#pragma unroll
        for (int j = 0; j < 8; ++j) acc[i][j] = 0.f;

    for (int k0 = 0; k0 < K; k0 += 16) {
        float4 a0 = *(const float4*)&A[(long)(o0 + ar) * K + k0 + aq];
        float4 a1 = *(const float4*)&A[(long)(o0 + ar) * K + k0 + aq + 4];
        As[aq + 0][ar] = a0.x; As[aq + 1][ar] = a0.y;
        As[aq + 2][ar] = a0.z; As[aq + 3][ar] = a0.w;
        As[aq + 4][ar] = a1.x; As[aq + 5][ar] = a1.y;
        As[aq + 6][ar] = a1.z; As[aq + 7][ar] = a1.w;
        *(float4*)&Bs[bk][bn]     = *(const float4*)&Bp[(long)(k0 + bk) * N + n0 + bn];
        *(float4*)&Bs[bk][bn + 4] = *(const float4*)&Bp[(long)(k0 + bk) * N + n0 + bn + 4];
        __syncthreads();
#pragma unroll 4
        for (int k = 0; k < 16; ++k) {
            float a[8], b[8];
            *(float4*)&a[0] = *(const float4*)&As[k][ty * 8];
            *(float4*)&a[4] = *(const float4*)&As[k][ty * 8 + 4];
            *(float4*)&b[0] = *(const float4*)&Bs[k][tx * 8];
            *(float4*)&b[4] = *(const float4*)&Bs[k][tx * 8 + 4];
#pragma unroll
            for (int i = 0; i < 8; ++i)
#pragma unroll
                for (int j = 0; j < 8; ++j)
                    acc[i][j] = fmaf(a[i], b[j], acc[i][j]);
        }
        __syncthreads();
    }

#pragma unroll
    for (int i = 0; i < 8; ++i) {
        int o = o0 + ty * 8 + i;
        float sv = scale ? scale[o] : 1.0f;
        float bv = biasp[o];
        float r[8];
#pragma unroll
        for (int j = 0; j < 8; ++j)
            r[j] = fmaxf(fmaf(acc[i][j], sv, bv), 0.f);
        *(float4*)&Cp[(long)o * N + n0 + tx * 8]     = *(float4*)&r[0];
        *(float4*)&Cp[(long)o * N + n0 + tx * 8 + 4] = *(float4*)&r[4];
    }
}

// =====================================================================
// GEMM B: 64(O) x 256(N) tile, 256 threads, 8x8 micro-tile, Ktile 16.
// flags bit0: kmax (write max over groups of 4 n to C[o,2048]); bit1: relu.
// add (optional): per-point pre-scale addend T[z][o][n>>2].
// =====================================================================
__global__ void __launch_bounds__(256) gemmB(
    const float* __restrict__ A, const float* __restrict__ B, float* __restrict__ C,
    const float* __restrict__ scale, const float* __restrict__ bias,
    int K, int N, long sB, long sC, int flags,
    const float* __restrict__ add, long sAdd)
{
    __shared__ float As[16][64];
    __shared__ float Bs[16][256];
    const float* Bp = B + (long)blockIdx.z * sB;
    float* Cp = C + (long)blockIdx.z * sC;
    const int n0 = blockIdx.x * 256;
    const int tid = threadIdx.x;
    const int tx = tid & 31, ty = tid >> 5;   // ty 0..7 (o), tx 0..31 (n)

    const int ar = tid >> 2;             // 0..63
    const int aq = (tid & 3) * 4;        // 0,4,8,12
    const int bk = tid >> 4;             // 0..15
    const int bn = (tid & 15) * 16;      // 0..240

    float acc[8][8];
#pragma unroll
    for (int i = 0; i < 8; ++i)
#pragma unroll
        for (int j = 0; j < 8; ++j) acc[i][j] = 0.f;

    for (int k0 = 0; k0 < K; k0 += 16) {
        float4 a0 = *(const float4*)&A[(long)ar * K + k0 + aq];
        As[aq + 0][ar] = a0.x; As[aq + 1][ar] = a0.y;
        As[aq + 2][ar] = a0.z; As[aq + 3][ar] = a0.w;
#pragma unroll
        for (int q = 0; q < 4; ++q)
            *(float4*)&Bs[bk][bn + q * 4] =
                *(const float4*)&Bp[(long)(k0 + bk) * N + n0 + bn + q * 4];
        __syncthreads();
#pragma unroll 4
        for (int k = 0; k < 16; ++k) {
            float a[8], b[8];
            *(float4*)&a[0] = *(const float4*)&As[k][ty * 8];
            *(float4*)&a[4] = *(const float4*)&As[k][ty * 8 + 4];
            *(float4*)&b[0] = *(const float4*)&Bs[k][tx * 8];
            *(float4*)&b[4] = *(const float4*)&Bs[k][tx * 8 + 4];
#pragma unroll
            for (int i = 0; i < 8; ++i)
#pragma unroll
                for (int j = 0; j < 8; ++j)
                    acc[i][j] = fmaf(a[i], b[j], acc[i][j]);
        }
        __syncthreads();
    }

    const bool kmax = (flags & 1) != 0;
    const bool relu = (flags & 2) != 0;
#pragma unroll
    for (int i = 0; i < 8; ++i) {
        int o = ty * 8 + i;
        float sv = scale ? scale[o] : 1.0f;
        float bv = bias ? bias[o] : 0.0f;
        float t0 = 0.f, t1 = 0.f;
        if (add) {
            const float* ap = add + (long)blockIdx.z * sAdd + (long)o * 2048
                              + (n0 >> 2) + tx * 2;
            t0 = ap[0]; t1 = ap[1];
        }
        float r[8];
#pragma unroll
        for (int j = 0; j < 8; ++j) {
            float v = fmaf(acc[i][j] + ((j < 4) ? t0 : t1), sv, bv);
            r[j] = relu ? fmaxf(v, 0.f) : v;
        }
        if (kmax) {
            int p = (n0 >> 2) + tx * 2;
            Cp[(long)o * 2048 + p]     = fmaxf(fmaxf(r[0], r[1]), fmaxf(r[2], r[3]));
            Cp[(long)o * 2048 + p + 1] = fmaxf(fmaxf(r[4], r[5]), fmaxf(r[6], r[7]));
        } else {
            *(float4*)&Cp[(long)o * N + n0 + tx * 8]     = *(float4*)&r[0];
            *(float4*)&Cp[(long)o * N + n0 + tx * 8 + 4] = *(float4*)&r[4];
        }
    }
}

// ---------------- xx[b,n] = sum_c h2^2 (same FMA chain order as the dot) --------
__global__ void xx_kernel()
{
    int t = blockIdx.x * blockDim.x + threadIdx.x;   // 8*2048
    int b = t >> 11, n = t & 2047;
    const float* h = d_h2 + (long)b * 64 * 2048;
    float acc = 0.f;
#pragma unroll
    for (int c = 0; c < 64; ++c) {
        float v = h[c * 2048 + n];
        acc = fmaf(v, v, acc);
    }
    d_xx[t] = acc;
}

// ---------------- g1[b,c] = max_n h2[b,c,n] ----------------
__global__ void gmax_kernel()
{
    int bc = blockIdx.x;          // 0..511
    int tid = threadIdx.x;        // 256 threads
    const float4* p = (const float4*)(d_h2 + (long)bc * 2048);
    float4 v0 = p[tid];
    float4 v1 = p[tid + 256];
    float m = fmaxf(fmaxf(fmaxf(v0.x, v0.y), fmaxf(v0.z, v0.w)),
                    fmaxf(fmaxf(v1.x, v1.y), fmaxf(v1.z, v1.w)));
    __shared__ float sm[256];
    sm[tid] = m;
    __syncthreads();
    for (int s = 128; s > 0; s >>= 1) {
        if (tid < s) sm[tid] = fmaxf(sm[tid], sm[tid + s]);
        __syncthreads();
    }
    if (tid == 0) d_g1[bc] = sm[0];
}

// ---------------- stable top-4 insert (strict > keeps earliest index on ties) ----
__device__ __forceinline__ void topk_insert(float pd, int m,
    float& v0, float& v1, float& v2, float& v3,
    int& i0, int& i1, int& i2, int& i3)
{
    if (pd > v3) {
        if (pd > v1) {
            if (pd > v0) {
                v3 = v2; i3 = i2; v2 = v1; i2 = i1; v1 = v0; i1 = i0;
                v0 = pd; i0 = m;
            } else {
                v3 = v2; i3 = i2; v2 = v1; i2 = i1;
                v1 = pd; i1 = m;
            }
        } else {
            if (pd > v2) { v3 = v2; i3 = i2; v2 = pd; i2 = m; }
            else         { v3 = pd; i3 = m; }
        }
    }
}

// ---------------- pairwise distances + top-4, 4-way m-split, 2 points/thread ----
// grid (16, 8), block 256. lane (tid&63) owns points nbase, nbase+1;
// quarter (tid>>6) owns m range quarter*512..+512.
__global__ void __launch_bounds__(256) pairwise_topk()
{
    __shared__ float sm[64][256];    // col = quarter*64 + j
    __shared__ float sxx[256];
    __shared__ float mv[3][128][4];
    __shared__ int   mi[3][128][4];

    const int b = blockIdx.y;
    const int tid = threadIdx.x;
    const int lane = tid & 63;
    const int quarter = tid >> 6;     // 0..3
    const int nbase = blockIdx.x * 128 + lane * 2;
    const float* h = d_h2 + (long)b * 64 * 2048;

    float hn0[64], hn1[64];
#pragma unroll
    for (int c = 0; c < 64; ++c) {
        float2 v = *(const float2*)&h[c * 2048 + nbase];
        hn0[c] = v.x; hn1[c] = v.y;
    }
    const float xn0 = d_xx[b * 2048 + nbase];
    const float xn1 = d_xx[b * 2048 + nbase + 1];

    float a0 = -1e30f, a1 = -1e30f, a2 = -1e30f, a3 = -1e30f;
    int   ai0 = 0, ai1 = 0, ai2 = 0, ai3 = 0;
    float c0 = -1e30f, c1 = -1e30f, c2 = -1e30f, c3 = -1e30f;
    int   ci0 = 0, ci1 = 0, ci2 = 0, ci3 = 0;

    const int base = quarter * 64;

    for (int it = 0; it < 8; ++it) {
        __syncthreads();
        for (int idx = tid; idx < 64 * 256; idx += 256) {
            int c = idx >> 8, col = idx & 255;
            int m = (col >> 6) * 512 + it * 64 + (col & 63);
            sm[c][col] = h[c * 2048 + m];
        }
        {
            int m = (tid >> 6) * 512 + it * 64 + (tid & 63);
            sxx[tid] = d_xx[b * 2048 + m];
        }
        __syncthreads();

        const int m0 = quarter * 512 + it * 64;
#pragma unroll 1
        for (int mm = 0; mm < 64; mm += 8) {
            float dot0[8], dot1[8];
#pragma unroll
            for (int j = 0; j < 8; ++j) { dot0[j] = 0.f; dot1[j] = 0.f; }
#pragma unroll
            for (int c = 0; c < 64; ++c) {
                float4 s0 = *(const float4*)&sm[c][base + mm];      // broadcast
                float4 s1 = *(const float4*)&sm[c][base + mm + 4];  // broadcast
                float h0 = hn0[c], h1 = hn1[c];
                dot0[0] = fmaf(h0, s0.x, dot0[0]);
                dot0[1] = fmaf(h0, s0.y, dot0[1]);
                dot0[2] = fmaf(h0, s0.z, dot0[2]);
                dot0[3] = fmaf(h0, s0.w, dot0[3]);
                dot0[4] = fmaf(h0, s1.x, dot0[4]);
                dot0[5] = fmaf(h0, s1.y, dot0[5]);
                dot0[6] = fmaf(h0, s1.z, dot0[6]);
                dot0[7] = fmaf(h0, s1.w, dot0[7]);
                dot1[0] = fmaf(h1, s0.x, dot1[0]);
                dot1[1] = fmaf(h1, s0.y, dot1[1]);
                dot1[2] = fmaf(h1, s0.z, dot1[2]);
                dot1[3] = fmaf(h1, s0.w, dot1[3]);
                dot1[4] = fmaf(h1, s1.x, dot1[4]);
                dot1[5] = fmaf(h1, s1.y, dot1[5]);
                dot1[6] = fmaf(h1, s1.z, dot1[6]);
                dot1[7] = fmaf(h1, s1.w, dot1[7]);
            }
#pragma unroll
            for (int j = 0; j < 8; ++j) {
                float sx = sxx[base + mm + j];
                int m = m0 + mm + j;
                float pd0 = fmaf(2.0f, dot0[j], -xn0) - sx;
                topk_insert(pd0, m, a0, a1, a2, a3, ai0, ai1, ai2, ai3);
                float pd1 = fmaf(2.0f, dot1[j], -xn1) - sx;
                topk_insert(pd1, m, c0, c1, c2, c3, ci0, ci1, ci2, ci3);
            }
        }
    }

    // merge: quarters 1..3 publish; quarter 0 merges in ascending-m order.
    const int p0 = lane * 2, p1 = lane * 2 + 1;
    __syncthreads();
    if (quarter > 0) {
        int q = quarter - 1;
        mv[q][p0][0] = a0; mv[q][p0][1] = a1; mv[q][p0][2] = a2; mv[q][p0][3] = a3;
        mi[q][p0][0] = ai0; mi[q][p0][1] = ai1; mi[q][p0][2] = ai2; mi[q][p0][3] = ai3;
        mv[q][p1][0] = c0; mv[q][p1][1] = c1; mv[q][p1][2] = c2; mv[q][p1][3] = c3;
        mi[q][p1][0] = ci0; mi[q][p1][1] = ci1; mi[q][p1][2] = ci2; mi[q][p1][3] = ci3;
    }
    __syncthreads();
    if (quarter == 0) {
#pragma unroll
        for (int q = 0; q < 3; ++q)
#pragma unroll
            for (int j = 0; j < 4; ++j) {
                topk_insert(mv[q][p0][j], mi[q][p0][j],
                            a0, a1, a2, a3, ai0, ai1, ai2, ai3);
                topk_insert(mv[q][p1][j], mi[q][p1][j],
                            c0, c1, c2, c3, ci0, ci1, ci2, ci3);
            }
        int baseo = (b * 2048 + nbase) * 4;
        d_idx[baseo + 0] = ai0;
        d_idx[baseo + 1] = ai1;
        d_idx[baseo + 2] = ai2;
        d_idx[baseo + 3] = ai3;
        d_idx[baseo + 4] = ci0;
        d_idx[baseo + 5] = ci1;
        d_idx[baseo + 6] = ci2;
        d_idx[baseo + 7] = ci3;
    }
}

// ---------------- build gathered-nb features: feat[b,c,(n,k)] = h[c, idx] ------
__global__ void build_feat()
{
    long t = (long)blockIdx.x * blockDim.x + threadIdx.x;   // 8*64*8192
    int k = (int)(t & 3);
    int n = (int)((t >> 2) & 2047);
    int c = (int)((t >> 13) & 63);
    int b = (int)(t >> 19);
    const float* h = d_h2 + (long)b * 64 * 2048;
    int j = d_idx[((long)b * 2048 + n) * 4 + k];
    d_feat[t] = h[c * 2048 + j];
}

// ---------------- global-feature MLP: 64 -> 128 -> 128 ----------------
__global__ void gpath(const float* __restrict__ W3a, const float* __restrict__ s3a,
                      const float* __restrict__ b3a, const float* __restrict__ W3b,
                      const float* __restrict__ s3b, const float* __restrict__ b3b)
{
    __shared__ float gin[64];
    __shared__ float gmid[128];
    int b = blockIdx.x, tid = threadIdx.x;
    if (tid < 64) gin[tid] = d_g1[b * 64 + tid];
    __syncthreads();
    float acc = 0.f;
#pragma unroll
    for (int c = 0; c < 64; ++c) acc = fmaf(W3a[tid * 64 + c], gin[c], acc);
    gmid[tid] = fmaxf(fmaf(acc, s3a[tid], b3a[tid]), 0.f);
    __syncthreads();
    acc = 0.f;
#pragma unroll
    for (int c = 0; c < 128; ++c) acc = fmaf(W3b[tid * 128 + c], gmid[c], acc);
    d_g2[b * 128 + tid] = fmaxf(fmaf(acc, s3b[tid], b3b[tid]), 0.f);
}

// ---------------- gb[b][o] = bias4a[o] + W4a[o,64:192] . g2[b,:] ----------------
__global__ void gbias(const float* __restrict__ W4a, const float* __restrict__ bias4a)
{
    int b = blockIdx.x;       // 8
    int o = threadIdx.x;      // 256
    float acc = bias4a[o];
#pragma unroll
    for (int c = 0; c < 128; ++c)
        acc = fmaf(W4a[o * 192 + 64 + c], d_g2[b * 128 + c], acc);
    d_gb[b * 256 + o] = acc;
}

// ---------------- head: out[b,o,n] = W4b[o,:] @ h4[b,:,n] + bias ----------------
__global__ void out_kernel(const float* __restrict__ W4b,
                           const float* __restrict__ bias4b,
                           float* __restrict__ out)
{
    int t = blockIdx.x * blockDim.x + threadIdx.x;  // 8*2048
    int b = t >> 11, n = t & 2047;
    const float* h = d_h4 + (long)b * 256 * 2048;
    float a0 = bias4b[0], a1 = bias4b[1], a2 = bias4b[2];
#pragma unroll 4
    for (int c = 0; c < 256; ++c) {
        float hv = h[c * 2048 + n];
        a0 = fmaf(W4b[c], hv, a0);
        a1 = fmaf(W4b[256 + c], hv, a1);
        a2 = fmaf(W4b[512 + c], hv, a2);
    }
    out[((long)b * 3 + 0) * 2048 + n] = a0;
    out[((long)b * 3 + 1) * 2048 + n] = a1;
    out[((long)b * 3 + 2) * 2048 + n] = a2;
}

// ---------------- host launcher ----------------
extern "C" void kernel_launch(void* const* d_in, const int* in_sizes, int n_in,
                              void* d_out, int out_size)
{
    const float* x      = (const float*)d_in[0];
    const float* W_dup  = (const float*)d_in[1];
    const float* s_dup  = (const float*)d_in[2];
    const float* b_dup  = (const float*)d_in[3];
    const float* W_c1   = (const float*)d_in[4];
    const float* s_c1   = (const float*)d_in[5];
    const float* b_c1   = (const float*)d_in[6];
    const float* W2a    = (const float*)d_in[7];
    const float* s2a    = (const float*)d_in[8];
    const float* b2a    = (const float*)d_in[9];
    const float* W2b    = (const float*)d_in[10];
    const float* s2b    = (const float*)d_in[11];
    const float* b2b    = (const float*)d_in[12];
    const float* W2c    = (const float*)d_in[13];
    const float* s2c    = (const float*)d_in[14];
    const float* b2c    = (const float*)d_in[15];
    const float* W3a    = (const float*)d_in[16];
    const float* s3a    = (const float*)d_in[17];
    const float* b3a    = (const float*)d_in[18];
    const float* W3b    = (const float*)d_in[19];
    const float* s3b    = (const float*)d_in[20];
    const float* b3b    = (const float*)d_in[21];
    const float* W4a    = (const float*)d_in[22];
    const float* bias4a = (const float*)d_in[23];
    const float* W4b    = (const float*)d_in[24];
    const float* bias4b = (const float*)d_in[25];

    float *p_h1, *p_h2, *p_feat, *p_fa, *p_fb, *p_local, *p_h4;
    float *p_T, *p_gb, *p_W4a_c, *p_W2a_nb, *p_W2a_diff;
    cudaGetSymbolAddress((void**)&p_h1, d_h1);
    cudaGetSymbolAddress((void**)&p_h2, d_h2);
    cudaGetSymbolAddress((void**)&p_feat, d_feat);
    cudaGetSymbolAddress((void**)&p_fa, d_fa);
    cudaGetSymbolAddress((void**)&p_fb, d_fb);
    cudaGetSymbolAddress((void**)&p_local, d_local);
    cudaGetSymbolAddress((void**)&p_h4, d_h4);
    cudaGetSymbolAddress((void**)&p_T, d_T);
    cudaGetSymbolAddress((void**)&p_gb, d_gb);
    cudaGetSymbolAddress((void**)&p_W4a_c, d_W4a_c);
    cudaGetSymbolAddress((void**)&p_W2a_nb, d_W2a_nb);
    cudaGetSymbolAddress((void**)&p_W2a_diff, d_W2a_diff);

    prep_weights<<<80, 256>>>(W4a, W2a);

    // L1: (256x128) @ x[b](128x1024) -> h1
    gemmA<<<dim3(8, 2, 8), 256>>>(W_dup, x, p_h1, s_dup, b_dup,
                                  128, 1024, 131072L, 262144L, 0L);
    // L2: (64x128) @ h1[b] reinterpreted as (128x2048) -> h2
    gemmB<<<dim3(8, 1, 8), 256>>>(W_c1, p_h1, p_h2, s_c1, b_c1,
                                  128, 2048, 262144L, 131072L, 2, nullptr, 0L);
    xx_kernel<<<64, 256>>>();
    gmax_kernel<<<512, 256>>>();
    pairwise_topk<<<dim3(16, 8), 256>>>();
    build_feat<<<16384, 256>>>();
    // T[b,o,n] = (W2a_diff) @ h2  (raw, no scale/bias/relu)
    gemmB<<<dim3(8, 1, 8), 256>>>(p_W2a_diff, p_h2, p_T, nullptr, nullptr,
                                  64, 2048, 131072L, 131072L, 0, nullptr, 0L);
    // conv2a: (64x64) @ feat(nb)[b](64x8192) + T broadcast -> fa
    gemmB<<<dim3(32, 1, 8), 256>>>(p_W2a_nb, p_feat, p_fa, s2a, b2a,
                                   64, 8192, 524288L, 524288L, 2, p_T, 131072L);
    // conv2b: (64x64) @ fa -> fb
    gemmB<<<dim3(32, 1, 8), 256>>>(W2b, p_fa, p_fb, s2b, b2b,
                                   64, 8192, 524288L, 524288L, 2, nullptr, 0L);
    // conv2c: (64x64) @ fb -> local (fused max over k in epilogue)
    gemmB<<<dim3(32, 1, 8), 256>>>(W2c, p_fb, p_local, s2c, b2c,
                                   64, 8192, 524288L, 131072L, 3, nullptr, 0L);
    gpath<<<8, 128>>>(W3a, s3a, b3a, W3b, s3b, b3b);
    gbias<<<8, 256>>>(W4a, bias4a);
    // head hidden: (256x64) @ local[b](64x2048), per-batch folded bias -> h4
    gemmA<<<dim3(16, 2, 8), 256>>>(p_W4a_c, p_local, p_h4, nullptr, p_gb,
                                   64, 2048, 131072L, 524288L, 256L);
    out_kernel<<<64, 256>>>(W4b, bias4b, (float*)d_out);
}